// round 1
// baseline (speedup 1.0000x reference)
#include <cuda_runtime.h>
#include <cuda_bf16.h>

// ---------------- problem-size constants (scratch sized to these) ----------
#define MAXN 100352            // >= 100000 nodes
#define MAXE 1703936           // >= 1600000 edges
#define MAXG 1024              // >= 1000 graphs
#define F0 128
#define F1 64
#define F2 32
#define FM 128

// ---------------- static device scratch (no allocations allowed) ----------
static __device__ float d_degw[MAXN];
static __device__ int   d_cnt[MAXN];
static __device__ float d_dinv[MAXN];
static __device__ int   d_rowptr[MAXN + 1];
static __device__ int   d_rowcur[MAXN + 1];
static __device__ int   d_blocksum[128];
static __device__ int   d_blockoff[130];
static __device__ int   d_csr_src[MAXE];
static __device__ float d_csr_w[MAXE];
static __device__ float d_m0[MAXN * F1];   // x @ W0          [N,64]
static __device__ float d_h0[MAXN * F1];   // relu(agg0 + b0) [N,64]
static __device__ float d_m1[MAXN * F2];   // h0 @ W1         [N,32]
static __device__ float d_g [MAXG * F2];   // pooled          [G,32]

// ---------------- small utility kernels -----------------------------------
__global__ void k_zero(int n, int gsz) {
    int i = blockIdx.x * blockDim.x + threadIdx.x;
    if (i < n) { d_degw[i] = 0.f; d_cnt[i] = 0; }
    if (i < gsz) d_g[i] = 0.f;
}

__global__ void k_deg(const int* __restrict__ src, const int* __restrict__ dst,
                      const float* __restrict__ w, int E) {
    int e = blockIdx.x * blockDim.x + threadIdx.x;
    if (e >= E) return;
    int d = dst[e];
    atomicAdd(&d_degw[d], w[e]);
    atomicAdd(&d_cnt[d], 1);
}

__global__ void k_dinv(int n) {
    int i = blockIdx.x * blockDim.x + threadIdx.x;
    if (i >= n) return;
    float deg = d_degw[i] + 1.0f;            // + self-loop weight
    float di = (deg > 0.f) ? rsqrtf(fmaxf(deg, 1e-12f)) : 0.f;
    d_dinv[i] = di;
}

// ---------------- exclusive scan of d_cnt -> d_rowptr ----------------------
__global__ void k_scan_partial(int n) {
    __shared__ int s[512];
    int t = threadIdx.x;
    int base = blockIdx.x * 2048;
    int v[4]; int sum = 0;
#pragma unroll
    for (int i = 0; i < 4; i++) {
        int idx = base + t * 4 + i;
        v[i] = (idx < n) ? d_cnt[idx] : 0;
        sum += v[i];
    }
    s[t] = sum; __syncthreads();
#pragma unroll
    for (int off = 1; off < 512; off <<= 1) {
        int add = (t >= off) ? s[t - off] : 0;
        __syncthreads();
        s[t] += add;
        __syncthreads();
    }
    int excl = s[t] - sum;
#pragma unroll
    for (int i = 0; i < 4; i++) {
        int idx = base + t * 4 + i;
        if (idx < n) d_rowptr[idx] = excl;
        excl += v[i];
    }
    if (t == 511) d_blocksum[blockIdx.x] = s[511];
}

__global__ void k_scan_block(int nb) {
    __shared__ int s[64];
    int t = threadIdx.x;
    int v = (t < nb) ? d_blocksum[t] : 0;
    s[t] = v; __syncthreads();
#pragma unroll
    for (int off = 1; off < 64; off <<= 1) {
        int add = (t >= off) ? s[t - off] : 0;
        __syncthreads();
        s[t] += add;
        __syncthreads();
    }
    d_blockoff[t] = s[t] - v;          // exclusive
    if (t == 63) d_blockoff[64] = s[63]; // total
}

__global__ void k_scan_add(int n) {
    int i = blockIdx.x * blockDim.x + threadIdx.x;
    if (i < n) {
        int r = d_rowptr[i] + d_blockoff[i >> 11];
        d_rowptr[i] = r;
        d_rowcur[i] = r;
    }
    if (i == 0) d_rowptr[n] = d_blockoff[64];
}

__global__ void k_fill(const int* __restrict__ src, const int* __restrict__ dst,
                       const float* __restrict__ w, int E) {
    int e = blockIdx.x * blockDim.x + threadIdx.x;
    if (e >= E) return;
    int s = src[e], d = dst[e];
    int p = atomicAdd(&d_rowcur[d], 1);
    d_csr_src[p] = s;
    d_csr_w[p] = d_dinv[s] * w[e] * d_dinv[d];
}

// ---------------- GEMM0: m0[N,64] = x[N,128] @ W0[128,64] ------------------
__global__ void __launch_bounds__(256) k_gemm0(const float* __restrict__ x,
                                               const float* __restrict__ W, int n) {
    __shared__ float xs[64][68];
    __shared__ float ws[64][68];
    int tid = threadIdx.x;
    int rowBase = blockIdx.x * 64;
    int tx = tid & 15, ty = tid >> 4;
    int i0 = ty * 4, j0 = tx * 4;
    float acc[4][4] = {};
    for (int kk = 0; kk < 128; kk += 64) {
#pragma unroll
        for (int it = 0; it < 4; it++) {
            int idx = tid + it * 256;        // 0..1023 : 64 rows x 16 float4
            int r = idx >> 4, kv = idx & 15;
            float4 v = make_float4(0.f, 0.f, 0.f, 0.f);
            int grow = rowBase + r;
            if (grow < n) v = *reinterpret_cast<const float4*>(x + (size_t)grow * 128 + kk + kv * 4);
            *reinterpret_cast<float4*>(&xs[r][kv * 4]) = v;
        }
#pragma unroll
        for (int it = 0; it < 4; it++) {
            int idx = tid + it * 256;        // 0..1023 : 64 rows x 16 float4
            int r = idx >> 4, c = idx & 15;
            float4 v = *reinterpret_cast<const float4*>(W + (size_t)(kk + r) * 64 + c * 4);
            *reinterpret_cast<float4*>(&ws[r][c * 4]) = v;
        }
        __syncthreads();
#pragma unroll 16
        for (int k = 0; k < 64; k++) {
            float a0 = xs[i0][k], a1 = xs[i0 + 1][k], a2 = xs[i0 + 2][k], a3 = xs[i0 + 3][k];
            float4 b = *reinterpret_cast<const float4*>(&ws[k][j0]);
            acc[0][0] += a0 * b.x; acc[0][1] += a0 * b.y; acc[0][2] += a0 * b.z; acc[0][3] += a0 * b.w;
            acc[1][0] += a1 * b.x; acc[1][1] += a1 * b.y; acc[1][2] += a1 * b.z; acc[1][3] += a1 * b.w;
            acc[2][0] += a2 * b.x; acc[2][1] += a2 * b.y; acc[2][2] += a2 * b.z; acc[2][3] += a2 * b.w;
            acc[3][0] += a3 * b.x; acc[3][1] += a3 * b.y; acc[3][2] += a3 * b.z; acc[3][3] += a3 * b.w;
        }
        __syncthreads();
    }
#pragma unroll
    for (int r = 0; r < 4; r++) {
        int grow = rowBase + i0 + r;
        if (grow < n) {
            float4 o = make_float4(acc[r][0], acc[r][1], acc[r][2], acc[r][3]);
            *reinterpret_cast<float4*>(d_m0 + (size_t)grow * 64 + j0) = o;
        }
    }
}

// ---------------- agg0: h0 = relu(sum_{e->n} w*m0[src] + self + b0) --------
__global__ void __launch_bounds__(256) k_agg0(const float* __restrict__ b0, int n) {
    int warp = (blockIdx.x * blockDim.x + threadIdx.x) >> 5;
    int lane = threadIdx.x & 31;
    if (warp >= n) return;
    const float2* m = reinterpret_cast<const float2*>(d_m0);
    float di = d_dinv[warp];
    float sw = di * di;
    float2 mm = m[(size_t)warp * 32 + lane];
    float ax = sw * mm.x, ay = sw * mm.y;
    int e = d_rowptr[warp], end = d_rowptr[warp + 1];
    for (; e + 4 <= end; e += 4) {
        int s0 = d_csr_src[e], s1 = d_csr_src[e + 1], s2 = d_csr_src[e + 2], s3 = d_csr_src[e + 3];
        float w0 = d_csr_w[e], w1 = d_csr_w[e + 1], w2 = d_csr_w[e + 2], w3 = d_csr_w[e + 3];
        float2 v0 = m[(size_t)s0 * 32 + lane];
        float2 v1 = m[(size_t)s1 * 32 + lane];
        float2 v2 = m[(size_t)s2 * 32 + lane];
        float2 v3 = m[(size_t)s3 * 32 + lane];
        ax += w0 * v0.x; ay += w0 * v0.y;
        ax += w1 * v1.x; ay += w1 * v1.y;
        ax += w2 * v2.x; ay += w2 * v2.y;
        ax += w3 * v3.x; ay += w3 * v3.y;
    }
    for (; e < end; e++) {
        int s = d_csr_src[e]; float w = d_csr_w[e];
        float2 v = m[(size_t)s * 32 + lane];
        ax += w * v.x; ay += w * v.y;
    }
    float bx = b0[2 * lane], by = b0[2 * lane + 1];
    ax = fmaxf(ax + bx, 0.f); ay = fmaxf(ay + by, 0.f);
    reinterpret_cast<float2*>(d_h0)[(size_t)warp * 32 + lane] = make_float2(ax, ay);
}

// ---------------- GEMM1: m1[N,32] = h0[N,64] @ W1[64,32] -------------------
__global__ void __launch_bounds__(128) k_gemm1(const float* __restrict__ W, int n) {
    __shared__ float xs[64][68];
    __shared__ float ws[64][36];
    int tid = threadIdx.x;
    int rowBase = blockIdx.x * 64;
    int tx = tid & 7, ty = tid >> 3;
    int i0 = ty * 4, j0 = tx * 4;
#pragma unroll
    for (int it = 0; it < 8; it++) {
        int idx = tid + it * 128;          // 0..1023 : 64 rows x 16 float4
        int r = idx >> 4, kv = idx & 15;
        float4 v = make_float4(0.f, 0.f, 0.f, 0.f);
        int grow = rowBase + r;
        if (grow < n) v = *reinterpret_cast<const float4*>(d_h0 + (size_t)grow * 64 + kv * 4);
        *reinterpret_cast<float4*>(&xs[r][kv * 4]) = v;
    }
#pragma unroll
    for (int it = 0; it < 4; it++) {
        int idx = tid + it * 128;          // 0..511 : 64 rows x 8 float4
        int r = idx >> 3, c = idx & 7;
        float4 v = *reinterpret_cast<const float4*>(W + (size_t)r * 32 + c * 4);
        *reinterpret_cast<float4*>(&ws[r][c * 4]) = v;
    }
    __syncthreads();
    float acc[4][4] = {};
#pragma unroll 16
    for (int k = 0; k < 64; k++) {
        float a0 = xs[i0][k], a1 = xs[i0 + 1][k], a2 = xs[i0 + 2][k], a3 = xs[i0 + 3][k];
        float4 b = *reinterpret_cast<const float4*>(&ws[k][j0]);
        acc[0][0] += a0 * b.x; acc[0][1] += a0 * b.y; acc[0][2] += a0 * b.z; acc[0][3] += a0 * b.w;
        acc[1][0] += a1 * b.x; acc[1][1] += a1 * b.y; acc[1][2] += a1 * b.z; acc[1][3] += a1 * b.w;
        acc[2][0] += a2 * b.x; acc[2][1] += a2 * b.y; acc[2][2] += a2 * b.z; acc[2][3] += a2 * b.w;
        acc[3][0] += a3 * b.x; acc[3][1] += a3 * b.y; acc[3][2] += a3 * b.z; acc[3][3] += a3 * b.w;
    }
#pragma unroll
    for (int r = 0; r < 4; r++) {
        int grow = rowBase + i0 + r;
        if (grow < n) {
            float4 o = make_float4(acc[r][0], acc[r][1], acc[r][2], acc[r][3]);
            *reinterpret_cast<float4*>(d_m1 + (size_t)grow * 32 + j0) = o;
        }
    }
}

// ---------------- agg1 + pooling: g[graph] += relu(agg + b1) ---------------
__global__ void __launch_bounds__(256) k_agg1(const float* __restrict__ b1,
                                              const int* __restrict__ ngi, int n) {
    int warp = (blockIdx.x * blockDim.x + threadIdx.x) >> 5;
    int lane = threadIdx.x & 31;
    if (warp >= n) return;
    float di = d_dinv[warp];
    float sw = di * di;
    float acc = sw * d_m1[(size_t)warp * 32 + lane];
    int e = d_rowptr[warp], end = d_rowptr[warp + 1];
    for (; e + 4 <= end; e += 4) {
        int s0 = d_csr_src[e], s1 = d_csr_src[e + 1], s2 = d_csr_src[e + 2], s3 = d_csr_src[e + 3];
        float w0 = d_csr_w[e], w1 = d_csr_w[e + 1], w2 = d_csr_w[e + 2], w3 = d_csr_w[e + 3];
        acc += w0 * d_m1[(size_t)s0 * 32 + lane];
        acc += w1 * d_m1[(size_t)s1 * 32 + lane];
        acc += w2 * d_m1[(size_t)s2 * 32 + lane];
        acc += w3 * d_m1[(size_t)s3 * 32 + lane];
    }
    for (; e < end; e++) {
        acc += d_csr_w[e] * d_m1[(size_t)d_csr_src[e] * 32 + lane];
    }
    float h = fmaxf(acc + b1[lane], 0.f);
    int g = ngi[warp];
    atomicAdd(&d_g[(size_t)g * 32 + lane], h);
}

// ---------------- MLP head: logits = relu(g@Wm1+bm1)@Wm2+bm2 ---------------
__global__ void __launch_bounds__(128) k_mlp(const float* __restrict__ Wm1,
                                             const float* __restrict__ bm1,
                                             const float* __restrict__ Wm2,
                                             const float* __restrict__ bm2,
                                             float* __restrict__ out, int G) {
    int gi = blockIdx.x;
    if (gi >= G) return;
    __shared__ float gs[32];
    __shared__ float red0[4], red1[4];
    int t = threadIdx.x;
    if (t < 32) gs[t] = d_g[(size_t)gi * 32 + t];
    __syncthreads();
    float acc = bm1[t];
#pragma unroll
    for (int k = 0; k < 32; k++) acc += gs[k] * Wm1[k * 128 + t];
    float h = fmaxf(acc, 0.f);
    float p0 = h * Wm2[t * 2 + 0];
    float p1 = h * Wm2[t * 2 + 1];
#pragma unroll
    for (int off = 16; off > 0; off >>= 1) {
        p0 += __shfl_down_sync(0xffffffffu, p0, off);
        p1 += __shfl_down_sync(0xffffffffu, p1, off);
    }
    if ((t & 31) == 0) { red0[t >> 5] = p0; red1[t >> 5] = p1; }
    __syncthreads();
    if (t == 0) {
        out[gi * 2 + 0] = red0[0] + red0[1] + red0[2] + red0[3] + bm2[0];
        out[gi * 2 + 1] = red1[0] + red1[1] + red1[2] + red1[3] + bm2[1];
    }
}

// ---------------------------------------------------------------------------
extern "C" void kernel_launch(void* const* d_in, const int* in_sizes, int n_in,
                              void* d_out, int out_size) {
    const float* x   = (const float*)d_in[0];
    const int*   ei  = (const int*)d_in[1];
    const float* ew  = (const float*)d_in[2];
    const int*   ngi = (const int*)d_in[3];
    const float* W0  = (const float*)d_in[4];
    const float* b0  = (const float*)d_in[5];
    const float* W1  = (const float*)d_in[6];
    const float* b1  = (const float*)d_in[7];
    const float* Wm1 = (const float*)d_in[8];
    const float* bm1 = (const float*)d_in[9];
    const float* Wm2 = (const float*)d_in[10];
    const float* bm2 = (const float*)d_in[11];
    float* out = (float*)d_out;

    int N = in_sizes[3];            // node_graph_index count
    int E = in_sizes[1] / 2;        // edge_index is [2, E]
    int G = out_size / 2;
    if (N > MAXN) N = MAXN;
    if (E > MAXE) E = MAXE;
    if (G > MAXG) G = MAXG;

    const int* e_src = ei;
    const int* e_dst = ei + E;

    int nb = (N + 2047) / 2048;     // scan blocks (<=64)

    k_zero<<<(N + 255) / 256, 256>>>(N, G * 32);
    k_deg<<<(E + 255) / 256, 256>>>(e_src, e_dst, ew, E);
    k_dinv<<<(N + 255) / 256, 256>>>(N);
    k_scan_partial<<<nb, 512>>>(N);
    k_scan_block<<<1, 64>>>(nb);
    k_scan_add<<<(N + 255) / 256, 256>>>(N);
    k_fill<<<(E + 255) / 256, 256>>>(e_src, e_dst, ew, E);
    k_gemm0<<<(N + 63) / 64, 256>>>(x, W0, N);
    k_agg0<<<(N + 7) / 8, 256>>>(b0, N);
    k_gemm1<<<(N + 63) / 64, 128>>>(W1, N);
    k_agg1<<<(N + 7) / 8, 256>>>(b1, ngi, N);
    k_mlp<<<G, 128>>>(Wm1, bm1, Wm2, bm2, out, G);
}

// round 2
// speedup vs baseline: 1.0424x; 1.0424x over previous
#include <cuda_runtime.h>
#include <cuda_fp16.h>
#include <cuda_bf16.h>

// ---------------- problem-size constants (scratch sized to these) ----------
#define MAXN 100352            // >= 100000 nodes
#define MAXE 1703936           // >= 1600000 edges
#define MAXG 1024              // >= 1000 graphs
#define F1 64
#define F2 32

// ---------------- static device scratch (no allocations allowed) ----------
static __device__ float  d_degw[MAXN];
static __device__ int    d_cnt[MAXN];
static __device__ float  d_dinv[MAXN];
static __device__ int    d_rowptr[MAXN + 1];
static __device__ int    d_rowcur[MAXN + 1];
static __device__ int    d_blocksum[128];
static __device__ int    d_blockoff[130];
static __device__ int    d_csr_src[MAXE];
static __device__ float  d_csr_w[MAXE];
static __device__ __half d_m0[MAXN * F1];   // x @ W0          [N,64]  fp16
static __device__ float  d_h0[MAXN * F1];   // relu(agg0 + b0) [N,64]  fp32
static __device__ __half d_m1[MAXN * F2];   // h0 @ W1         [N,32]  fp16
static __device__ float  d_g [MAXG * F2];   // pooled          [G,32]

// ---------------- small utility kernels -----------------------------------
__global__ void k_zero(int n) {
    int i = blockIdx.x * blockDim.x + threadIdx.x;
    if (i < n) { d_degw[i] = 0.f; d_cnt[i] = 0; }
}

__global__ void k_deg(const int* __restrict__ dst,
                      const float* __restrict__ w, int E) {
    int e = blockIdx.x * blockDim.x + threadIdx.x;
    if (e >= E) return;
    int d = dst[e];
    atomicAdd(&d_degw[d], w[e]);
    atomicAdd(&d_cnt[d], 1);
}

// ---------------- exclusive scan of d_cnt -> d_rowptr ----------------------
__global__ void k_scan_partial(int n) {
    __shared__ int s[512];
    int t = threadIdx.x;
    int base = blockIdx.x * 2048;
    int v[4]; int sum = 0;
#pragma unroll
    for (int i = 0; i < 4; i++) {
        int idx = base + t * 4 + i;
        v[i] = (idx < n) ? d_cnt[idx] : 0;
        sum += v[i];
    }
    s[t] = sum; __syncthreads();
#pragma unroll
    for (int off = 1; off < 512; off <<= 1) {
        int add = (t >= off) ? s[t - off] : 0;
        __syncthreads();
        s[t] += add;
        __syncthreads();
    }
    int excl = s[t] - sum;
#pragma unroll
    for (int i = 0; i < 4; i++) {
        int idx = base + t * 4 + i;
        if (idx < n) d_rowptr[idx] = excl;
        excl += v[i];
    }
    if (t == 511) d_blocksum[blockIdx.x] = s[511];
}

__global__ void k_scan_block(int nb) {
    __shared__ int s[64];
    int t = threadIdx.x;
    int v = (t < nb) ? d_blocksum[t] : 0;
    s[t] = v; __syncthreads();
#pragma unroll
    for (int off = 1; off < 64; off <<= 1) {
        int add = (t >= off) ? s[t - off] : 0;
        __syncthreads();
        s[t] += add;
        __syncthreads();
    }
    d_blockoff[t] = s[t] - v;            // exclusive
    if (t == 63) d_blockoff[64] = s[63]; // total
}

// finalize rowptr, compute dinv, zero pooled buffer (all elementwise over N)
__global__ void k_scan_add(int n, int gsz) {
    int i = blockIdx.x * blockDim.x + threadIdx.x;
    if (i < n) {
        int r = d_rowptr[i] + d_blockoff[i >> 11];
        d_rowptr[i] = r;
        d_rowcur[i] = r;
        float deg = d_degw[i] + 1.0f;       // + self-loop weight
        d_dinv[i] = (deg > 0.f) ? rsqrtf(fmaxf(deg, 1e-12f)) : 0.f;
    }
    if (i < gsz) d_g[i] = 0.f;
    if (i == 0) d_rowptr[n] = d_blockoff[64];
}

// ---------------- GEMM0: m0[N,64] = x[N,128] @ W0[128,64]  (fp16 out) ------
__global__ void __launch_bounds__(256) k_gemm0(const float* __restrict__ x,
                                               const float* __restrict__ W, int n) {
    __shared__ float xs[64][68];
    __shared__ float ws[64][68];
    int tid = threadIdx.x;
    int rowBase = blockIdx.x * 64;
    int tx = tid & 15, ty = tid >> 4;
    int i0 = ty * 4, j0 = tx * 4;
    float acc[4][4] = {};
    for (int kk = 0; kk < 128; kk += 64) {
#pragma unroll
        for (int it = 0; it < 4; it++) {
            int idx = tid + it * 256;        // 64 rows x 16 float4
            int r = idx >> 4, kv = idx & 15;
            float4 v = make_float4(0.f, 0.f, 0.f, 0.f);
            int grow = rowBase + r;
            if (grow < n) v = *reinterpret_cast<const float4*>(x + (size_t)grow * 128 + kk + kv * 4);
            *reinterpret_cast<float4*>(&xs[r][kv * 4]) = v;
        }
#pragma unroll
        for (int it = 0; it < 4; it++) {
            int idx = tid + it * 256;        // 64 rows x 16 float4
            int r = idx >> 4, c = idx & 15;
            float4 v = *reinterpret_cast<const float4*>(W + (size_t)(kk + r) * 64 + c * 4);
            *reinterpret_cast<float4*>(&ws[r][c * 4]) = v;
        }
        __syncthreads();
#pragma unroll 16
        for (int k = 0; k < 64; k++) {
            float a0 = xs[i0][k], a1 = xs[i0 + 1][k], a2 = xs[i0 + 2][k], a3 = xs[i0 + 3][k];
            float4 b = *reinterpret_cast<const float4*>(&ws[k][j0]);
            acc[0][0] += a0 * b.x; acc[0][1] += a0 * b.y; acc[0][2] += a0 * b.z; acc[0][3] += a0 * b.w;
            acc[1][0] += a1 * b.x; acc[1][1] += a1 * b.y; acc[1][2] += a1 * b.z; acc[1][3] += a1 * b.w;
            acc[2][0] += a2 * b.x; acc[2][1] += a2 * b.y; acc[2][2] += a2 * b.z; acc[2][3] += a2 * b.w;
            acc[3][0] += a3 * b.x; acc[3][1] += a3 * b.y; acc[3][2] += a3 * b.z; acc[3][3] += a3 * b.w;
        }
        __syncthreads();
    }
#pragma unroll
    for (int r = 0; r < 4; r++) {
        int grow = rowBase + i0 + r;
        if (grow < n) {
            uint2 o;
            __half2 p0 = __floats2half2_rn(acc[r][0], acc[r][1]);
            __half2 p1 = __floats2half2_rn(acc[r][2], acc[r][3]);
            o.x = *reinterpret_cast<unsigned*>(&p0);
            o.y = *reinterpret_cast<unsigned*>(&p1);
            *reinterpret_cast<uint2*>(d_m0 + (size_t)grow * 64 + j0) = o;
        }
    }
}

// ---------------- k_fill: CSR fill with normalized weights -----------------
__global__ void k_fill(const int* __restrict__ src, const int* __restrict__ dst,
                       const float* __restrict__ w, int E) {
    int e = blockIdx.x * blockDim.x + threadIdx.x;
    if (e >= E) return;
    int s = src[e], d = dst[e];
    int p = atomicAdd(&d_rowcur[d], 1);
    d_csr_src[p] = s;
    d_csr_w[p] = d_dinv[s] * w[e] * d_dinv[d];
}

// ---------------- agg0: h0 = relu(sum w*m0[src] + self + b0) ---------------
__global__ void __launch_bounds__(256) k_agg0(const float* __restrict__ b0, int n) {
    int warp = (blockIdx.x * blockDim.x + threadIdx.x) >> 5;
    int lane = threadIdx.x & 31;
    if (warp >= n) return;
    const __half2* m = reinterpret_cast<const __half2*>(d_m0);
    float di = d_dinv[warp];
    float sw = di * di;
    float2 mm = __half22float2(m[(size_t)warp * 32 + lane]);
    float ax = sw * mm.x, ay = sw * mm.y;
    int e = d_rowptr[warp], end = d_rowptr[warp + 1];
    for (; e + 4 <= end; e += 4) {
        int s0 = d_csr_src[e], s1 = d_csr_src[e + 1], s2 = d_csr_src[e + 2], s3 = d_csr_src[e + 3];
        float w0 = d_csr_w[e], w1 = d_csr_w[e + 1], w2 = d_csr_w[e + 2], w3 = d_csr_w[e + 3];
        float2 v0 = __half22float2(m[(size_t)s0 * 32 + lane]);
        float2 v1 = __half22float2(m[(size_t)s1 * 32 + lane]);
        float2 v2 = __half22float2(m[(size_t)s2 * 32 + lane]);
        float2 v3 = __half22float2(m[(size_t)s3 * 32 + lane]);
        ax += w0 * v0.x; ay += w0 * v0.y;
        ax += w1 * v1.x; ay += w1 * v1.y;
        ax += w2 * v2.x; ay += w2 * v2.y;
        ax += w3 * v3.x; ay += w3 * v3.y;
    }
    for (; e < end; e++) {
        int s = d_csr_src[e]; float w = d_csr_w[e];
        float2 v = __half22float2(m[(size_t)s * 32 + lane]);
        ax += w * v.x; ay += w * v.y;
    }
    float bx = b0[2 * lane], by = b0[2 * lane + 1];
    ax = fmaxf(ax + bx, 0.f); ay = fmaxf(ay + by, 0.f);
    reinterpret_cast<float2*>(d_h0)[(size_t)warp * 32 + lane] = make_float2(ax, ay);
}

// ---------------- GEMM1: m1[N,32] = h0[N,64] @ W1[64,32]  (fp16 out) -------
__global__ void __launch_bounds__(128) k_gemm1(const float* __restrict__ W, int n) {
    __shared__ float xs[64][68];
    __shared__ float ws[64][36];
    int tid = threadIdx.x;
    int rowBase = blockIdx.x * 64;
    int tx = tid & 7, ty = tid >> 3;
    int i0 = ty * 4, j0 = tx * 4;
#pragma unroll
    for (int it = 0; it < 8; it++) {
        int idx = tid + it * 128;          // 64 rows x 16 float4
        int r = idx >> 4, kv = idx & 15;
        float4 v = make_float4(0.f, 0.f, 0.f, 0.f);
        int grow = rowBase + r;
        if (grow < n) v = *reinterpret_cast<const float4*>(d_h0 + (size_t)grow * 64 + kv * 4);
        *reinterpret_cast<float4*>(&xs[r][kv * 4]) = v;
    }
#pragma unroll
    for (int it = 0; it < 4; it++) {
        int idx = tid + it * 128;          // 64 rows x 8 float4
        int r = idx >> 3, c = idx & 7;
        float4 v = *reinterpret_cast<const float4*>(W + (size_t)r * 32 + c * 4);
        *reinterpret_cast<float4*>(&ws[r][c * 4]) = v;
    }
    __syncthreads();
    float acc[4][4] = {};
#pragma unroll 16
    for (int k = 0; k < 64; k++) {
        float a0 = xs[i0][k], a1 = xs[i0 + 1][k], a2 = xs[i0 + 2][k], a3 = xs[i0 + 3][k];
        float4 b = *reinterpret_cast<const float4*>(&ws[k][j0]);
        acc[0][0] += a0 * b.x; acc[0][1] += a0 * b.y; acc[0][2] += a0 * b.z; acc[0][3] += a0 * b.w;
        acc[1][0] += a1 * b.x; acc[1][1] += a1 * b.y; acc[1][2] += a1 * b.z; acc[1][3] += a1 * b.w;
        acc[2][0] += a2 * b.x; acc[2][1] += a2 * b.y; acc[2][2] += a2 * b.z; acc[2][3] += a2 * b.w;
        acc[3][0] += a3 * b.x; acc[3][1] += a3 * b.y; acc[3][2] += a3 * b.z; acc[3][3] += a3 * b.w;
    }
#pragma unroll
    for (int r = 0; r < 4; r++) {
        int grow = rowBase + i0 + r;
        if (grow < n) {
            uint2 o;
            __half2 p0 = __floats2half2_rn(acc[r][0], acc[r][1]);
            __half2 p1 = __floats2half2_rn(acc[r][2], acc[r][3]);
            o.x = *reinterpret_cast<unsigned*>(&p0);
            o.y = *reinterpret_cast<unsigned*>(&p1);
            *reinterpret_cast<uint2*>(d_m1 + (size_t)grow * 32 + j0) = o;
        }
    }
}

// ---------------- agg1 + pooling: g[graph] += relu(agg + b1) ---------------
__global__ void __launch_bounds__(256) k_agg1(const float* __restrict__ b1,
                                              const int* __restrict__ ngi, int n) {
    int warp = (blockIdx.x * blockDim.x + threadIdx.x) >> 5;
    int lane = threadIdx.x & 31;
    if (warp >= n) return;
    float di = d_dinv[warp];
    float sw = di * di;
    float acc = sw * __half2float(d_m1[(size_t)warp * 32 + lane]);
    int e = d_rowptr[warp], end = d_rowptr[warp + 1];
    for (; e + 4 <= end; e += 4) {
        int s0 = d_csr_src[e], s1 = d_csr_src[e + 1], s2 = d_csr_src[e + 2], s3 = d_csr_src[e + 3];
        float w0 = d_csr_w[e], w1 = d_csr_w[e + 1], w2 = d_csr_w[e + 2], w3 = d_csr_w[e + 3];
        acc += w0 * __half2float(d_m1[(size_t)s0 * 32 + lane]);
        acc += w1 * __half2float(d_m1[(size_t)s1 * 32 + lane]);
        acc += w2 * __half2float(d_m1[(size_t)s2 * 32 + lane]);
        acc += w3 * __half2float(d_m1[(size_t)s3 * 32 + lane]);
    }
    for (; e < end; e++) {
        acc += d_csr_w[e] * __half2float(d_m1[(size_t)d_csr_src[e] * 32 + lane]);
    }
    float h = fmaxf(acc + b1[lane], 0.f);
    int g = ngi[warp];
    atomicAdd(&d_g[(size_t)g * 32 + lane], h);
}

// ---------------- MLP head: logits = relu(g@Wm1+bm1)@Wm2+bm2 ---------------
__global__ void __launch_bounds__(128) k_mlp(const float* __restrict__ Wm1,
                                             const float* __restrict__ bm1,
                                             const float* __restrict__ Wm2,
                                             const float* __restrict__ bm2,
                                             float* __restrict__ out, int G) {
    int gi = blockIdx.x;
    if (gi >= G) return;
    __shared__ float gs[32];
    __shared__ float red0[4], red1[4];
    int t = threadIdx.x;
    if (t < 32) gs[t] = d_g[(size_t)gi * 32 + t];
    __syncthreads();
    float acc = bm1[t];
#pragma unroll
    for (int k = 0; k < 32; k++) acc += gs[k] * Wm1[k * 128 + t];
    float h = fmaxf(acc, 0.f);
    float p0 = h * Wm2[t * 2 + 0];
    float p1 = h * Wm2[t * 2 + 1];
#pragma unroll
    for (int off = 16; off > 0; off >>= 1) {
        p0 += __shfl_down_sync(0xffffffffu, p0, off);
        p1 += __shfl_down_sync(0xffffffffu, p1, off);
    }
    if ((t & 31) == 0) { red0[t >> 5] = p0; red1[t >> 5] = p1; }
    __syncthreads();
    if (t == 0) {
        out[gi * 2 + 0] = red0[0] + red0[1] + red0[2] + red0[3] + bm2[0];
        out[gi * 2 + 1] = red1[0] + red1[1] + red1[2] + red1[3] + bm2[1];
    }
}

// ---------------------------------------------------------------------------
extern "C" void kernel_launch(void* const* d_in, const int* in_sizes, int n_in,
                              void* d_out, int out_size) {
    const float* x   = (const float*)d_in[0];
    const int*   ei  = (const int*)d_in[1];
    const float* ew  = (const float*)d_in[2];
    const int*   ngi = (const int*)d_in[3];
    const float* W0  = (const float*)d_in[4];
    const float* b0  = (const float*)d_in[5];
    const float* W1  = (const float*)d_in[6];
    const float* b1  = (const float*)d_in[7];
    const float* Wm1 = (const float*)d_in[8];
    const float* bm1 = (const float*)d_in[9];
    const float* Wm2 = (const float*)d_in[10];
    const float* bm2 = (const float*)d_in[11];
    float* out = (float*)d_out;

    int N = in_sizes[3];            // node_graph_index count
    int E = in_sizes[1] / 2;        // edge_index is [2, E]
    int G = out_size / 2;
    if (N > MAXN) N = MAXN;
    if (E > MAXE) E = MAXE;
    if (G > MAXG) G = MAXG;

    const int* e_src = ei;
    const int* e_dst = ei + E;

    int nb = (N + 2047) / 2048;     // scan blocks (<=64)

    k_zero<<<(N + 255) / 256, 256>>>(N);                            // 0
    k_deg<<<(E + 255) / 256, 256>>>(e_dst, ew, E);                  // 1
    k_scan_partial<<<nb, 512>>>(N);                                 // 2
    k_scan_block<<<1, 64>>>(nb);                                    // 3
    k_scan_add<<<(N + 255) / 256, 256>>>(N, G * 32);                // 4
    k_gemm0<<<(N + 63) / 64, 256>>>(x, W0, N);                      // 5  <- profiled by ncu -s 5
    k_fill<<<(E + 255) / 256, 256>>>(e_src, e_dst, ew, E);          // 6
    k_agg0<<<(N + 7) / 8, 256>>>(b0, N);                            // 7
    k_gemm1<<<(N + 63) / 64, 128>>>(W1, N);                         // 8
    k_agg1<<<(N + 7) / 8, 256>>>(b1, ngi, N);                       // 9
    k_mlp<<<G, 128>>>(Wm1, bm1, Wm2, bm2, out, G);                  // 10
}

// round 3
// speedup vs baseline: 1.2347x; 1.1844x over previous
#include <cuda_runtime.h>
#include <cuda_fp16.h>
#include <cuda_bf16.h>
#include <mma.h>

using namespace nvcuda;

// ---------------- problem-size constants (scratch sized to these) ----------
#define MAXN 100352            // >= 100000 nodes
#define MAXE 1703936           // >= 1600000 edges
#define MAXG 1024              // >= 1000 graphs
#define F1 64
#define F2 32

// ---------------- static device scratch (no allocations allowed) ----------
static __device__ float  d_degw[MAXN];
static __device__ int    d_cnt[MAXN];
static __device__ float  d_dinv[MAXN];
static __device__ int    d_rowptr[MAXN + 1];
static __device__ int    d_rowcur[MAXN + 1];
static __device__ int    d_blocksum[128];
static __device__ int    d_blockoff[130];
static __device__ int    d_csr_src[MAXE];
static __device__ float  d_csr_w[MAXE];
static __device__ __half d_m0[MAXN * F1];   // x @ W0          [N,64]  fp16
static __device__ __half d_h0[MAXN * F1];   // relu(agg0 + b0) [N,64]  fp16
static __device__ __half d_m1[MAXN * F2];   // h0 @ W1         [N,32]  fp16
static __device__ float  d_g [MAXG * F2];   // pooled          [G,32]

// ---------------- small utility kernels -----------------------------------
__global__ void k_zero(int n) {
    int i = blockIdx.x * blockDim.x + threadIdx.x;
    if (i < n) { d_degw[i] = 0.f; d_cnt[i] = 0; }
}

__global__ void k_deg(const int* __restrict__ dst,
                      const float* __restrict__ w, int E) {
    int e = blockIdx.x * blockDim.x + threadIdx.x;
    if (e >= E) return;
    int d = dst[e];
    atomicAdd(&d_degw[d], w[e]);
    atomicAdd(&d_cnt[d], 1);
}

// ---------------- exclusive scan of d_cnt -> d_rowptr ----------------------
__global__ void k_scan_partial(int n) {
    __shared__ int s[512];
    int t = threadIdx.x;
    int base = blockIdx.x * 2048;
    int v[4]; int sum = 0;
#pragma unroll
    for (int i = 0; i < 4; i++) {
        int idx = base + t * 4 + i;
        v[i] = (idx < n) ? d_cnt[idx] : 0;
        sum += v[i];
    }
    s[t] = sum; __syncthreads();
#pragma unroll
    for (int off = 1; off < 512; off <<= 1) {
        int add = (t >= off) ? s[t - off] : 0;
        __syncthreads();
        s[t] += add;
        __syncthreads();
    }
    int excl = s[t] - sum;
#pragma unroll
    for (int i = 0; i < 4; i++) {
        int idx = base + t * 4 + i;
        if (idx < n) d_rowptr[idx] = excl;
        excl += v[i];
    }
    if (t == 511) d_blocksum[blockIdx.x] = s[511];
}

__global__ void k_scan_block(int nb) {
    __shared__ int s[64];
    int t = threadIdx.x;
    int v = (t < nb) ? d_blocksum[t] : 0;
    s[t] = v; __syncthreads();
#pragma unroll
    for (int off = 1; off < 64; off <<= 1) {
        int add = (t >= off) ? s[t - off] : 0;
        __syncthreads();
        s[t] += add;
        __syncthreads();
    }
    d_blockoff[t] = s[t] - v;            // exclusive
    if (t == 63) d_blockoff[64] = s[63]; // total
}

// finalize rowptr, compute dinv, zero pooled buffer
__global__ void k_scan_add(int n, int gsz) {
    int i = blockIdx.x * blockDim.x + threadIdx.x;
    if (i < n) {
        int r = d_rowptr[i] + d_blockoff[i >> 11];
        d_rowptr[i] = r;
        d_rowcur[i] = r;
        float deg = d_degw[i] + 1.0f;       // + self-loop weight
        d_dinv[i] = (deg > 0.f) ? rsqrtf(fmaxf(deg, 1e-12f)) : 0.f;
    }
    if (i < gsz) d_g[i] = 0.f;
    if (i == 0) d_rowptr[n] = d_blockoff[64];
}

// ---------------- GEMM0 (tensor cores): m0[N,64] = x[N,128] @ W0[128,64] ---
// 64-row tile, full K=128 and N=64 in smem; fp16 MMA, fp32 accum, fp16 out.
__global__ void __launch_bounds__(256) k_gemm0(const float* __restrict__ x,
                                               const float* __restrict__ W, int n) {
    __shared__ __align__(16) char sm[64 * 136 * 2 + 128 * 72 * 2];
    __half (*xs)[136] = reinterpret_cast<__half(*)[136]>(sm);
    __half (*ws)[72]  = reinterpret_cast<__half(*)[72]>(sm + 64 * 136 * 2);
    float  (*os)[68]  = reinterpret_cast<float(*)[68]>(sm);      // aliases xs

    int tid = threadIdx.x;
    int rowBase = blockIdx.x * 64;

    // load x tile [64,128] fp32 -> fp16 smem : 64 rows x 32 float4
#pragma unroll
    for (int it = 0; it < 8; it++) {
        int idx = tid + it * 256;
        int r = idx >> 5, c = idx & 31;
        float4 v = make_float4(0.f, 0.f, 0.f, 0.f);
        int grow = rowBase + r;
        if (grow < n) v = *reinterpret_cast<const float4*>(x + (size_t)grow * 128 + c * 4);
        __half2 h0 = __floats2half2_rn(v.x, v.y);
        __half2 h1 = __floats2half2_rn(v.z, v.w);
        uint2 u; u.x = *reinterpret_cast<unsigned*>(&h0); u.y = *reinterpret_cast<unsigned*>(&h1);
        *reinterpret_cast<uint2*>(&xs[r][c * 4]) = u;
    }
    // load W [128,64] fp32 -> fp16 smem : 128 rows x 16 float4
#pragma unroll
    for (int it = 0; it < 8; it++) {
        int idx = tid + it * 256;
        int r = idx >> 4, c = idx & 15;
        float4 v = *reinterpret_cast<const float4*>(W + (size_t)r * 64 + c * 4);
        __half2 h0 = __floats2half2_rn(v.x, v.y);
        __half2 h1 = __floats2half2_rn(v.z, v.w);
        uint2 u; u.x = *reinterpret_cast<unsigned*>(&h0); u.y = *reinterpret_cast<unsigned*>(&h1);
        *reinterpret_cast<uint2*>(&ws[r][c * 4]) = u;
    }
    __syncthreads();

    int warp = tid >> 5;
    int rb = warp >> 1;          // 0..3 : row block (16 rows)
    int ch = warp & 1;           // 0..1 : column half (32 cols)

    wmma::fragment<wmma::accumulator, 16, 16, 16, float> c0, c1;
    wmma::fill_fragment(c0, 0.f);
    wmma::fill_fragment(c1, 0.f);
#pragma unroll
    for (int k = 0; k < 8; k++) {
        wmma::fragment<wmma::matrix_a, 16, 16, 16, __half, wmma::row_major> a;
        wmma::load_matrix_sync(a, &xs[rb * 16][k * 16], 136);
        wmma::fragment<wmma::matrix_b, 16, 16, 16, __half, wmma::row_major> b0, b1;
        wmma::load_matrix_sync(b0, &ws[k * 16][ch * 32], 72);
        wmma::load_matrix_sync(b1, &ws[k * 16][ch * 32 + 16], 72);
        wmma::mma_sync(c0, a, b0, c0);
        wmma::mma_sync(c1, a, b1, c1);
    }
    __syncthreads();             // xs no longer needed; reuse as float out
    wmma::store_matrix_sync(&os[rb * 16][ch * 32], c0, 68, wmma::mem_row_major);
    wmma::store_matrix_sync(&os[rb * 16][ch * 32 + 16], c1, 68, wmma::mem_row_major);
    __syncthreads();

    // write out fp16 : 64 rows x 32 half2
#pragma unroll
    for (int it = 0; it < 8; it++) {
        int idx = tid + it * 256;
        int r = idx >> 5, c2 = idx & 31;
        int grow = rowBase + r;
        if (grow < n) {
            __half2 h = __floats2half2_rn(os[r][c2 * 2], os[r][c2 * 2 + 1]);
            reinterpret_cast<__half2*>(d_m0 + (size_t)grow * 64)[c2] = h;
        }
    }
}

// ---------------- k_fill: CSR fill with normalized weights -----------------
__global__ void k_fill(const int* __restrict__ src, const int* __restrict__ dst,
                       const float* __restrict__ w, int E) {
    int e = blockIdx.x * blockDim.x + threadIdx.x;
    if (e >= E) return;
    int s = src[e], d = dst[e];
    int p = atomicAdd(&d_rowcur[d], 1);
    d_csr_src[p] = s;
    d_csr_w[p] = d_dinv[s] * w[e] * d_dinv[d];
}

// ---------------- agg0: h0 = relu(sum w*m0[src] + self + b0)  (fp16 out) ---
__global__ void __launch_bounds__(256) k_agg0(const float* __restrict__ b0, int n) {
    int warp = (blockIdx.x * blockDim.x + threadIdx.x) >> 5;
    int lane = threadIdx.x & 31;
    if (warp >= n) return;
    const __half2* m = reinterpret_cast<const __half2*>(d_m0);
    float di = d_dinv[warp];
    float sw = di * di;
    float2 mm = __half22float2(m[(size_t)warp * 32 + lane]);
    float ax = sw * mm.x, ay = sw * mm.y;
    int e = d_rowptr[warp], end = d_rowptr[warp + 1];
    for (; e + 4 <= end; e += 4) {
        int s0 = d_csr_src[e], s1 = d_csr_src[e + 1], s2 = d_csr_src[e + 2], s3 = d_csr_src[e + 3];
        float w0 = d_csr_w[e], w1 = d_csr_w[e + 1], w2 = d_csr_w[e + 2], w3 = d_csr_w[e + 3];
        float2 v0 = __half22float2(m[(size_t)s0 * 32 + lane]);
        float2 v1 = __half22float2(m[(size_t)s1 * 32 + lane]);
        float2 v2 = __half22float2(m[(size_t)s2 * 32 + lane]);
        float2 v3 = __half22float2(m[(size_t)s3 * 32 + lane]);
        ax += w0 * v0.x; ay += w0 * v0.y;
        ax += w1 * v1.x; ay += w1 * v1.y;
        ax += w2 * v2.x; ay += w2 * v2.y;
        ax += w3 * v3.x; ay += w3 * v3.y;
    }
    for (; e < end; e++) {
        int s = d_csr_src[e]; float w = d_csr_w[e];
        float2 v = __half22float2(m[(size_t)s * 32 + lane]);
        ax += w * v.x; ay += w * v.y;
    }
    float bx = b0[2 * lane], by = b0[2 * lane + 1];
    ax = fmaxf(ax + bx, 0.f); ay = fmaxf(ay + by, 0.f);
    reinterpret_cast<__half2*>(d_h0)[(size_t)warp * 32 + lane] = __floats2half2_rn(ax, ay);
}

// ---------------- GEMM1 (tensor cores): m1[N,32] = h0[N,64] @ W1[64,32] ----
__global__ void __launch_bounds__(128) k_gemm1(const float* __restrict__ W, int n) {
    __shared__ __align__(16) char sm[64 * 72 * 2 + 64 * 40 * 2];
    __half (*xs)[72] = reinterpret_cast<__half(*)[72]>(sm);
    __half (*ws)[40] = reinterpret_cast<__half(*)[40]>(sm + 64 * 72 * 2);
    float  (*os)[36] = reinterpret_cast<float(*)[36]>(sm);       // aliases xs

    int tid = threadIdx.x;
    int rowBase = blockIdx.x * 64;

    // load h0 tile [64,64] fp16 : 64 rows x 16 uint2 (4 halves each)
#pragma unroll
    for (int it = 0; it < 8; it++) {
        int idx = tid + it * 128;
        int r = idx >> 4, c = idx & 15;
        uint2 u = make_uint2(0u, 0u);
        int grow = rowBase + r;
        if (grow < n) u = *reinterpret_cast<const uint2*>(d_h0 + (size_t)grow * 64 + c * 4);
        *reinterpret_cast<uint2*>(&xs[r][c * 4]) = u;
    }
    // load W1 [64,32] fp32 -> fp16 : 64 rows x 8 float4
#pragma unroll
    for (int it = 0; it < 4; it++) {
        int idx = tid + it * 128;
        int r = idx >> 3, c = idx & 7;
        float4 v = *reinterpret_cast<const float4*>(W + (size_t)r * 32 + c * 4);
        __half2 h0 = __floats2half2_rn(v.x, v.y);
        __half2 h1 = __floats2half2_rn(v.z, v.w);
        uint2 u; u.x = *reinterpret_cast<unsigned*>(&h0); u.y = *reinterpret_cast<unsigned*>(&h1);
        *reinterpret_cast<uint2*>(&ws[r][c * 4]) = u;
    }
    __syncthreads();

    int warp = tid >> 5;         // 0..3, each: 16 rows x 32 cols
    wmma::fragment<wmma::accumulator, 16, 16, 16, float> c0, c1;
    wmma::fill_fragment(c0, 0.f);
    wmma::fill_fragment(c1, 0.f);
#pragma unroll
    for (int k = 0; k < 4; k++) {
        wmma::fragment<wmma::matrix_a, 16, 16, 16, __half, wmma::row_major> a;
        wmma::load_matrix_sync(a, &xs[warp * 16][k * 16], 72);
        wmma::fragment<wmma::matrix_b, 16, 16, 16, __half, wmma::row_major> b0, b1;
        wmma::load_matrix_sync(b0, &ws[k * 16][0], 40);
        wmma::load_matrix_sync(b1, &ws[k * 16][16], 40);
        wmma::mma_sync(c0, a, b0, c0);
        wmma::mma_sync(c1, a, b1, c1);
    }
    __syncthreads();
    wmma::store_matrix_sync(&os[warp * 16][0], c0, 36, wmma::mem_row_major);
    wmma::store_matrix_sync(&os[warp * 16][16], c1, 36, wmma::mem_row_major);
    __syncthreads();

    // write out fp16 : 64 rows x 16 half2
#pragma unroll
    for (int it = 0; it < 8; it++) {
        int idx = tid + it * 128;
        int r = idx >> 4, c2 = idx & 15;
        int grow = rowBase + r;
        if (grow < n) {
            __half2 h = __floats2half2_rn(os[r][c2 * 2], os[r][c2 * 2 + 1]);
            reinterpret_cast<__half2*>(d_m1 + (size_t)grow * 32)[c2] = h;
        }
    }
}

// ---------------- agg1 + pooling: g[graph] += relu(agg + b1) ---------------
__global__ void __launch_bounds__(256) k_agg1(const float* __restrict__ b1,
                                              const int* __restrict__ ngi, int n) {
    int warp = (blockIdx.x * blockDim.x + threadIdx.x) >> 5;
    int lane = threadIdx.x & 31;
    if (warp >= n) return;
    float di = d_dinv[warp];
    float sw = di * di;
    float acc = sw * __half2float(d_m1[(size_t)warp * 32 + lane]);
    int e = d_rowptr[warp], end = d_rowptr[warp + 1];
    for (; e + 4 <= end; e += 4) {
        int s0 = d_csr_src[e], s1 = d_csr_src[e + 1], s2 = d_csr_src[e + 2], s3 = d_csr_src[e + 3];
        float w0 = d_csr_w[e], w1 = d_csr_w[e + 1], w2 = d_csr_w[e + 2], w3 = d_csr_w[e + 3];
        acc += w0 * __half2float(d_m1[(size_t)s0 * 32 + lane]);
        acc += w1 * __half2float(d_m1[(size_t)s1 * 32 + lane]);
        acc += w2 * __half2float(d_m1[(size_t)s2 * 32 + lane]);
        acc += w3 * __half2float(d_m1[(size_t)s3 * 32 + lane]);
    }
    for (; e < end; e++) {
        acc += d_csr_w[e] * __half2float(d_m1[(size_t)d_csr_src[e] * 32 + lane]);
    }
    float h = fmaxf(acc + b1[lane], 0.f);
    int g = ngi[warp];
    atomicAdd(&d_g[(size_t)g * 32 + lane], h);
}

// ---------------- MLP head: logits = relu(g@Wm1+bm1)@Wm2+bm2 ---------------
__global__ void __launch_bounds__(128) k_mlp(const float* __restrict__ Wm1,
                                             const float* __restrict__ bm1,
                                             const float* __restrict__ Wm2,
                                             const float* __restrict__ bm2,
                                             float* __restrict__ out, int G) {
    int gi = blockIdx.x;
    if (gi >= G) return;
    __shared__ float gs[32];
    __shared__ float red0[4], red1[4];
    int t = threadIdx.x;
    if (t < 32) gs[t] = d_g[(size_t)gi * 32 + t];
    __syncthreads();
    float acc = bm1[t];
#pragma unroll
    for (int k = 0; k < 32; k++) acc += gs[k] * Wm1[k * 128 + t];
    float h = fmaxf(acc, 0.f);
    float p0 = h * Wm2[t * 2 + 0];
    float p1 = h * Wm2[t * 2 + 1];
#pragma unroll
    for (int off = 16; off > 0; off >>= 1) {
        p0 += __shfl_down_sync(0xffffffffu, p0, off);
        p1 += __shfl_down_sync(0xffffffffu, p1, off);
    }
    if ((t & 31) == 0) { red0[t >> 5] = p0; red1[t >> 5] = p1; }
    __syncthreads();
    if (t == 0) {
        out[gi * 2 + 0] = red0[0] + red0[1] + red0[2] + red0[3] + bm2[0];
        out[gi * 2 + 1] = red1[0] + red1[1] + red1[2] + red1[3] + bm2[1];
    }
}

// ---------------------------------------------------------------------------
extern "C" void kernel_launch(void* const* d_in, const int* in_sizes, int n_in,
                              void* d_out, int out_size) {
    const float* x   = (const float*)d_in[0];
    const int*   ei  = (const int*)d_in[1];
    const float* ew  = (const float*)d_in[2];
    const int*   ngi = (const int*)d_in[3];
    const float* W0  = (const float*)d_in[4];
    const float* b0  = (const float*)d_in[5];
    const float* W1  = (const float*)d_in[6];
    const float* b1  = (const float*)d_in[7];
    const float* Wm1 = (const float*)d_in[8];
    const float* bm1 = (const float*)d_in[9];
    const float* Wm2 = (const float*)d_in[10];
    const float* bm2 = (const float*)d_in[11];
    float* out = (float*)d_out;

    int N = in_sizes[3];            // node_graph_index count
    int E = in_sizes[1] / 2;        // edge_index is [2, E]
    int G = out_size / 2;
    if (N > MAXN) N = MAXN;
    if (E > MAXE) E = MAXE;
    if (G > MAXG) G = MAXG;

    const int* e_src = ei;
    const int* e_dst = ei + E;

    int nb = (N + 2047) / 2048;     // scan blocks (<=64)

    k_zero<<<(N + 255) / 256, 256>>>(N);                            // 0
    k_deg<<<(E + 255) / 256, 256>>>(e_dst, ew, E);                  // 1
    k_scan_partial<<<nb, 512>>>(N);                                 // 2
    k_scan_block<<<1, 64>>>(nb);                                    // 3
    k_scan_add<<<(N + 255) / 256, 256>>>(N, G * 32);                // 4
    k_gemm0<<<(N + 63) / 64, 256>>>(x, W0, N);                      // 5
    k_fill<<<(E + 255) / 256, 256>>>(e_src, e_dst, ew, E);          // 6
    k_agg0<<<(N + 7) / 8, 256>>>(b0, N);                            // 7
    k_gemm1<<<(N + 63) / 64, 128>>>(W1, N);                         // 8
    k_agg1<<<(N + 7) / 8, 256>>>(b1, ngi, N);                       // 9
    k_mlp<<<G, 128>>>(Wm1, bm1, Wm2, bm2, out, G);                  // 10
}

// round 4
// speedup vs baseline: 1.2604x; 1.0209x over previous
#include <cuda_runtime.h>
#include <cuda_fp16.h>
#include <cuda_bf16.h>
#include <mma.h>

using namespace nvcuda;

// ---------------- problem-size constants (scratch sized to these) ----------
#define MAXN 100352            // >= 100000 nodes
#define MAXE 1703936           // >= 1600000 edges
#define MAXG 1024              // >= 1000 graphs
#define F1 64
#define F2 32

// ---------------- static device scratch (no allocations allowed) ----------
static __device__ float  d_degw[MAXN];
static __device__ int    d_cnt[MAXN];
static __device__ float  d_dinv[MAXN];
static __device__ int    d_rowptr[MAXN + 1];
static __device__ int    d_rowcur[MAXN + 1];
static __device__ int    d_blocksum[128];
static __device__ int    d_csr_src[MAXE];
static __device__ float  d_csr_w[MAXE];
static __device__ __half d_m0[MAXN * F1];   // x @ W0          [N,64]  fp16
static __device__ __half d_m1[MAXN * F2];   // gcn layer 2 in  [N,32]  fp16
static __device__ float  d_g [MAXG * F2];   // pooled          [G,32]

// ---------------- small utility kernels -----------------------------------
__global__ void k_zero(int n) {
    int i = blockIdx.x * blockDim.x + threadIdx.x;
    if (i < n) { d_degw[i] = 0.f; d_cnt[i] = 0; }
}

__global__ void k_deg(const int* __restrict__ dst,
                      const float* __restrict__ w, int E) {
    int e = blockIdx.x * blockDim.x + threadIdx.x;
    if (e >= E) return;
    int d = dst[e];
    atomicAdd(&d_degw[d], w[e]);
    atomicAdd(&d_cnt[d], 1);
}

// ---------------- exclusive scan of d_cnt -> d_rowptr ----------------------
__global__ void k_scan_partial(int n) {
    __shared__ int s[512];
    int t = threadIdx.x;
    int base = blockIdx.x * 2048;
    int v[4]; int sum = 0;
#pragma unroll
    for (int i = 0; i < 4; i++) {
        int idx = base + t * 4 + i;
        v[i] = (idx < n) ? d_cnt[idx] : 0;
        sum += v[i];
    }
    s[t] = sum; __syncthreads();
#pragma unroll
    for (int off = 1; off < 512; off <<= 1) {
        int add = (t >= off) ? s[t - off] : 0;
        __syncthreads();
        s[t] += add;
        __syncthreads();
    }
    int excl = s[t] - sum;
#pragma unroll
    for (int i = 0; i < 4; i++) {
        int idx = base + t * 4 + i;
        if (idx < n) d_rowptr[idx] = excl;
        excl += v[i];
    }
    if (t == 511) d_blocksum[blockIdx.x] = s[511];
}

// finalize rowptr (block-local prefix over blocksums computed redundantly),
// compute dinv, zero pooled buffer
__global__ void k_scan_add(int n, int gsz, int nb) {
    __shared__ int s_pref;
    int base = blockIdx.x * 256;
    int t = threadIdx.x;
    if (t == 0) {
        int bucket = base >> 11;
        int p = 0;
        for (int j = 0; j < bucket; j++) p += d_blocksum[j];
        s_pref = p;
        if (blockIdx.x == 0) {
            int tot = 0;
            for (int j = 0; j < nb; j++) tot += d_blocksum[j];
            d_rowptr[n] = tot;
        }
    }
    __syncthreads();
    int i = base + t;
    if (i < n) {
        int r = d_rowptr[i] + s_pref;
        d_rowptr[i] = r;
        d_rowcur[i] = r;
        float deg = d_degw[i] + 1.0f;       // + self-loop weight
        d_dinv[i] = (deg > 0.f) ? rsqrtf(fmaxf(deg, 1e-12f)) : 0.f;
    }
    if (i < gsz) d_g[i] = 0.f;
}

// ---------------- GEMM0 (tensor cores): m0[N,64] = x[N,128] @ W0[128,64] ---
__global__ void __launch_bounds__(256) k_gemm0(const float* __restrict__ x,
                                               const float* __restrict__ W, int n) {
    __shared__ __align__(16) char sm[64 * 136 * 2 + 128 * 72 * 2];
    __half (*xs)[136] = reinterpret_cast<__half(*)[136]>(sm);
    __half (*ws)[72]  = reinterpret_cast<__half(*)[72]>(sm + 64 * 136 * 2);
    float  (*os)[68]  = reinterpret_cast<float(*)[68]>(sm);      // aliases xs

    int tid = threadIdx.x;
    int rowBase = blockIdx.x * 64;

#pragma unroll
    for (int it = 0; it < 8; it++) {
        int idx = tid + it * 256;
        int r = idx >> 5, c = idx & 31;
        float4 v = make_float4(0.f, 0.f, 0.f, 0.f);
        int grow = rowBase + r;
        if (grow < n) v = *reinterpret_cast<const float4*>(x + (size_t)grow * 128 + c * 4);
        __half2 h0 = __floats2half2_rn(v.x, v.y);
        __half2 h1 = __floats2half2_rn(v.z, v.w);
        uint2 u; u.x = *reinterpret_cast<unsigned*>(&h0); u.y = *reinterpret_cast<unsigned*>(&h1);
        *reinterpret_cast<uint2*>(&xs[r][c * 4]) = u;
    }
#pragma unroll
    for (int it = 0; it < 8; it++) {
        int idx = tid + it * 256;
        int r = idx >> 4, c = idx & 15;
        float4 v = *reinterpret_cast<const float4*>(W + (size_t)r * 64 + c * 4);
        __half2 h0 = __floats2half2_rn(v.x, v.y);
        __half2 h1 = __floats2half2_rn(v.z, v.w);
        uint2 u; u.x = *reinterpret_cast<unsigned*>(&h0); u.y = *reinterpret_cast<unsigned*>(&h1);
        *reinterpret_cast<uint2*>(&ws[r][c * 4]) = u;
    }
    __syncthreads();

    int warp = tid >> 5;
    int rb = warp >> 1;          // 0..3 : row block (16 rows)
    int ch = warp & 1;           // 0..1 : column half (32 cols)

    wmma::fragment<wmma::accumulator, 16, 16, 16, float> c0, c1;
    wmma::fill_fragment(c0, 0.f);
    wmma::fill_fragment(c1, 0.f);
#pragma unroll
    for (int k = 0; k < 8; k++) {
        wmma::fragment<wmma::matrix_a, 16, 16, 16, __half, wmma::row_major> a;
        wmma::load_matrix_sync(a, &xs[rb * 16][k * 16], 136);
        wmma::fragment<wmma::matrix_b, 16, 16, 16, __half, wmma::row_major> b0, b1;
        wmma::load_matrix_sync(b0, &ws[k * 16][ch * 32], 72);
        wmma::load_matrix_sync(b1, &ws[k * 16][ch * 32 + 16], 72);
        wmma::mma_sync(c0, a, b0, c0);
        wmma::mma_sync(c1, a, b1, c1);
    }
    __syncthreads();             // xs no longer needed; reuse as float out
    wmma::store_matrix_sync(&os[rb * 16][ch * 32], c0, 68, wmma::mem_row_major);
    wmma::store_matrix_sync(&os[rb * 16][ch * 32 + 16], c1, 68, wmma::mem_row_major);
    __syncthreads();

#pragma unroll
    for (int it = 0; it < 8; it++) {
        int idx = tid + it * 256;
        int r = idx >> 5, c2 = idx & 31;
        int grow = rowBase + r;
        if (grow < n) {
            __half2 h = __floats2half2_rn(os[r][c2 * 2], os[r][c2 * 2 + 1]);
            reinterpret_cast<__half2*>(d_m0 + (size_t)grow * 64)[c2] = h;
        }
    }
}

// ---------------- k_fill: CSR fill with normalized weights -----------------
__global__ void k_fill(const int* __restrict__ src, const int* __restrict__ dst,
                       const float* __restrict__ w, int E) {
    int e = blockIdx.x * blockDim.x + threadIdx.x;
    if (e >= E) return;
    int s = src[e], d = dst[e];
    int p = atomicAdd(&d_rowcur[d], 1);
    d_csr_src[p] = s;
    d_csr_w[p] = d_dinv[s] * w[e] * d_dinv[d];
}

// ------- fused agg0 + GEMM1: m1 = relu(agg(m0)+b0) @ W1  (fp16 out) --------
// 512 thr = 16 warps. Warp w aggregates nodes [base+4w, base+4w+4) into a
// 64x64 fp16 smem tile; warps 0..7 then run the 64x32x64 wmma GEMM.
__global__ void __launch_bounds__(512) k_agg0_gemm1(const float* __restrict__ b0,
                                                    const float* __restrict__ W, int n) {
    __shared__ __align__(16) char sm[64 * 72 * 2 + 64 * 40 * 2];
    __half (*xs)[72] = reinterpret_cast<__half(*)[72]>(sm);
    __half (*ws)[40] = reinterpret_cast<__half(*)[40]>(sm + 64 * 72 * 2);
    float  (*os)[36] = reinterpret_cast<float(*)[36]>(sm);       // aliases xs

    int tid = threadIdx.x;
    int base = blockIdx.x * 64;
    int warp = tid >> 5;
    int lane = tid & 31;

    // load W1 [64,32] fp32 -> fp16 : 512 float4 jobs, one per thread
    {
        int r = tid >> 3, c = tid & 7;
        float4 v = *reinterpret_cast<const float4*>(W + (size_t)r * 32 + c * 4);
        __half2 h0 = __floats2half2_rn(v.x, v.y);
        __half2 h1 = __floats2half2_rn(v.z, v.w);
        uint2 u; u.x = *reinterpret_cast<unsigned*>(&h0); u.y = *reinterpret_cast<unsigned*>(&h1);
        *reinterpret_cast<uint2*>(&ws[r][c * 4]) = u;
    }

    // aggregate 4 nodes per warp into xs rows
    const __half2* m = reinterpret_cast<const __half2*>(d_m0);
    float bx = b0[2 * lane], by = b0[2 * lane + 1];
#pragma unroll
    for (int i = 0; i < 4; i++) {
        int node = base + warp * 4 + i;
        int row = warp * 4 + i;
        if (node < n) {
            float di = d_dinv[node];
            float sw = di * di;
            float2 mm = __half22float2(m[(size_t)node * 32 + lane]);
            float ax = sw * mm.x, ay = sw * mm.y;
            int e = d_rowptr[node], end = d_rowptr[node + 1];
            for (; e + 4 <= end; e += 4) {
                int s0 = d_csr_src[e], s1 = d_csr_src[e + 1], s2 = d_csr_src[e + 2], s3 = d_csr_src[e + 3];
                float w0 = d_csr_w[e], w1 = d_csr_w[e + 1], w2 = d_csr_w[e + 2], w3 = d_csr_w[e + 3];
                float2 v0 = __half22float2(m[(size_t)s0 * 32 + lane]);
                float2 v1 = __half22float2(m[(size_t)s1 * 32 + lane]);
                float2 v2 = __half22float2(m[(size_t)s2 * 32 + lane]);
                float2 v3 = __half22float2(m[(size_t)s3 * 32 + lane]);
                ax += w0 * v0.x; ay += w0 * v0.y;
                ax += w1 * v1.x; ay += w1 * v1.y;
                ax += w2 * v2.x; ay += w2 * v2.y;
                ax += w3 * v3.x; ay += w3 * v3.y;
            }
            for (; e < end; e++) {
                int s = d_csr_src[e]; float w = d_csr_w[e];
                float2 v = __half22float2(m[(size_t)s * 32 + lane]);
                ax += w * v.x; ay += w * v.y;
            }
            ax = fmaxf(ax + bx, 0.f); ay = fmaxf(ay + by, 0.f);
            *reinterpret_cast<__half2*>(&xs[row][lane * 2]) = __floats2half2_rn(ax, ay);
        } else {
            *reinterpret_cast<__half2*>(&xs[row][lane * 2]) = __half2half2(__float2half(0.f));
        }
    }
    __syncthreads();

    // wmma: warps 0..7, each computes one 16x16 block of the 64x32 output
    if (warp < 8) {
        int rb = warp >> 1;      // 0..3
        int cb = warp & 1;       // 0..1
        wmma::fragment<wmma::accumulator, 16, 16, 16, float> c0;
        wmma::fill_fragment(c0, 0.f);
#pragma unroll
        for (int k = 0; k < 4; k++) {
            wmma::fragment<wmma::matrix_a, 16, 16, 16, __half, wmma::row_major> a;
            wmma::load_matrix_sync(a, &xs[rb * 16][k * 16], 72);
            wmma::fragment<wmma::matrix_b, 16, 16, 16, __half, wmma::row_major> b;
            wmma::load_matrix_sync(b, &ws[k * 16][cb * 16], 40);
            wmma::mma_sync(c0, a, b, c0);
        }
        __syncthreads();         // all mma reads of xs done
        wmma::store_matrix_sync(&os[rb * 16][cb * 16], c0, 36, wmma::mem_row_major);
    } else {
        __syncthreads();
    }
    __syncthreads();

    // write out m1 fp16 : 64 rows x 16 half2 = 1024 jobs
#pragma unroll
    for (int it = 0; it < 2; it++) {
        int idx = tid + it * 512;
        int r = idx >> 4, c2 = idx & 15;
        int grow = base + r;
        if (grow < n) {
            __half2 h = __floats2half2_rn(os[r][c2 * 2], os[r][c2 * 2 + 1]);
            reinterpret_cast<__half2*>(d_m1 + (size_t)grow * 32)[c2] = h;
        }
    }
}

// ---------------- agg1 + pooling: g[graph] += relu(agg + b1) ---------------
__global__ void __launch_bounds__(256) k_agg1(const float* __restrict__ b1,
                                              const int* __restrict__ ngi, int n) {
    int warp = (blockIdx.x * blockDim.x + threadIdx.x) >> 5;
    int lane = threadIdx.x & 31;
    if (warp >= n) return;
    float di = d_dinv[warp];
    float sw = di * di;
    float acc = sw * __half2float(d_m1[(size_t)warp * 32 + lane]);
    int e = d_rowptr[warp], end = d_rowptr[warp + 1];
    for (; e + 4 <= end; e += 4) {
        int s0 = d_csr_src[e], s1 = d_csr_src[e + 1], s2 = d_csr_src[e + 2], s3 = d_csr_src[e + 3];
        float w0 = d_csr_w[e], w1 = d_csr_w[e + 1], w2 = d_csr_w[e + 2], w3 = d_csr_w[e + 3];
        acc += w0 * __half2float(d_m1[(size_t)s0 * 32 + lane]);
        acc += w1 * __half2float(d_m1[(size_t)s1 * 32 + lane]);
        acc += w2 * __half2float(d_m1[(size_t)s2 * 32 + lane]);
        acc += w3 * __half2float(d_m1[(size_t)s3 * 32 + lane]);
    }
    for (; e < end; e++) {
        acc += d_csr_w[e] * __half2float(d_m1[(size_t)d_csr_src[e] * 32 + lane]);
    }
    float h = fmaxf(acc + b1[lane], 0.f);
    int g = ngi[warp];
    atomicAdd(&d_g[(size_t)g * 32 + lane], h);
}

// ---------------- MLP head: logits = relu(g@Wm1+bm1)@Wm2+bm2 ---------------
__global__ void __launch_bounds__(128) k_mlp(const float* __restrict__ Wm1,
                                             const float* __restrict__ bm1,
                                             const float* __restrict__ Wm2,
                                             const float* __restrict__ bm2,
                                             float* __restrict__ out, int G) {
    int gi = blockIdx.x;
    if (gi >= G) return;
    __shared__ float gs[32];
    __shared__ float red0[4], red1[4];
    int t = threadIdx.x;
    if (t < 32) gs[t] = d_g[(size_t)gi * 32 + t];
    __syncthreads();
    float acc = bm1[t];
#pragma unroll
    for (int k = 0; k < 32; k++) acc += gs[k] * Wm1[k * 128 + t];
    float h = fmaxf(acc, 0.f);
    float p0 = h * Wm2[t * 2 + 0];
    float p1 = h * Wm2[t * 2 + 1];
#pragma unroll
    for (int off = 16; off > 0; off >>= 1) {
        p0 += __shfl_down_sync(0xffffffffu, p0, off);
        p1 += __shfl_down_sync(0xffffffffu, p1, off);
    }
    if ((t & 31) == 0) { red0[t >> 5] = p0; red1[t >> 5] = p1; }
    __syncthreads();
    if (t == 0) {
        out[gi * 2 + 0] = red0[0] + red0[1] + red0[2] + red0[3] + bm2[0];
        out[gi * 2 + 1] = red1[0] + red1[1] + red1[2] + red1[3] + bm2[1];
    }
}

// ---------------------------------------------------------------------------
extern "C" void kernel_launch(void* const* d_in, const int* in_sizes, int n_in,
                              void* d_out, int out_size) {
    const float* x   = (const float*)d_in[0];
    const int*   ei  = (const int*)d_in[1];
    const float* ew  = (const float*)d_in[2];
    const int*   ngi = (const int*)d_in[3];
    const float* W0  = (const float*)d_in[4];
    const float* b0  = (const float*)d_in[5];
    const float* W1  = (const float*)d_in[6];
    const float* b1  = (const float*)d_in[7];
    const float* Wm1 = (const float*)d_in[8];
    const float* bm1 = (const float*)d_in[9];
    const float* Wm2 = (const float*)d_in[10];
    const float* bm2 = (const float*)d_in[11];
    float* out = (float*)d_out;

    int N = in_sizes[3];            // node_graph_index count
    int E = in_sizes[1] / 2;        // edge_index is [2, E]
    int G = out_size / 2;
    if (N > MAXN) N = MAXN;
    if (E > MAXE) E = MAXE;
    if (G > MAXG) G = MAXG;

    const int* e_src = ei;
    const int* e_dst = ei + E;

    int nb = (N + 2047) / 2048;     // scan blocks (<=64)

    // one-time side-stream + events (created outside any capture; reused in it)
    static cudaStream_t s_aux = nullptr;
    static cudaEvent_t  s_fork = nullptr, s_join = nullptr;
    if (s_aux == nullptr) {
        cudaStreamCreateWithFlags(&s_aux, cudaStreamNonBlocking);
        cudaEventCreateWithFlags(&s_fork, cudaEventDisableTiming);
        cudaEventCreateWithFlags(&s_join, cudaEventDisableTiming);
    }

    // fork: gemm0 runs concurrently with the CSR build chain
    cudaEventRecord(s_fork, 0);
    cudaStreamWaitEvent(s_aux, s_fork, 0);
    k_gemm0<<<(N + 63) / 64, 256, 0, s_aux>>>(x, W0, N);
    cudaEventRecord(s_join, s_aux);

    // CSR build chain on the default stream
    k_zero<<<(N + 255) / 256, 256>>>(N);
    k_deg<<<(E + 255) / 256, 256>>>(e_dst, ew, E);
    k_scan_partial<<<nb, 512>>>(N);
    k_scan_add<<<(N + 255) / 256, 256>>>(N, G * 32, nb);
    k_fill<<<(E + 255) / 256, 256>>>(e_src, e_dst, ew, E);

    // join, then the fused layer-1-agg + layer-2-GEMM, agg1+pool, MLP head
    cudaStreamWaitEvent(0, s_join, 0);
    k_agg0_gemm1<<<(N + 63) / 64, 512>>>(b0, W1, N);
    k_agg1<<<(N + 7) / 8, 256>>>(b1, ngi, N);
    k_mlp<<<G, 128>>>(Wm1, bm1, Wm2, bm2, out, G);
}

// round 7
// speedup vs baseline: 1.3876x; 1.1009x over previous
#include <cuda_runtime.h>
#include <cuda_fp16.h>
#include <cuda_bf16.h>
#include <mma.h>

using namespace nvcuda;

// ---------------- problem-size constants (scratch sized to these) ----------
#define MAXN 100352            // >= 100000 nodes
#define MAXE 1703936           // >= 1600000 edges
#define MAXG 1024              // >= 1000 graphs
#define F1 64
#define F2 32

// ---------------- static device scratch (no allocations allowed) ----------
static __device__ float  d_degw[MAXN];
static __device__ int    d_cnt[MAXN];
static __device__ float  d_dinv[MAXN];
static __device__ int    d_rowptr[MAXN + 1];
static __device__ int    d_rowcur[MAXN + 1];
static __device__ int    d_blocksum[128];
static __device__ int2   d_csr[MAXE];        // {src, edge_weight bits}
static __device__ __half d_m0[MAXN * F1];    // dinv .* (x @ W0)      [N,64]
static __device__ __half d_m1[MAXN * F2];    // dinv .* (h0 @ W1)     [N,32]
static __device__ float  d_g [MAXG * F2];    // pooled                [G,32]

// ---------------- small utility kernels -----------------------------------
__global__ void k_zero(int n) {
    int i = blockIdx.x * blockDim.x + threadIdx.x;
    if (i < n) { d_degw[i] = 0.f; d_cnt[i] = 0; }
}

__global__ void k_deg(const int* __restrict__ dst,
                      const float* __restrict__ w, int E) {
    int e = blockIdx.x * blockDim.x + threadIdx.x;
    if (e >= E) return;
    int d = dst[e];
    atomicAdd(&d_degw[d], w[e]);
    atomicAdd(&d_cnt[d], 1);
}

// ---------------- exclusive scan of d_cnt -> d_rowptr (shuffle-based) ------
__global__ void k_scan_partial(int n) {
    __shared__ int ssum[16];
    int t = threadIdx.x;
    int lane = t & 31, wid = t >> 5;
    int base = blockIdx.x * 2048;
    int v[4]; int sum = 0;
#pragma unroll
    for (int i = 0; i < 4; i++) {
        int idx = base + t * 4 + i;
        v[i] = (idx < n) ? d_cnt[idx] : 0;
        sum += v[i];
    }
    // warp inclusive scan of per-thread sums
    int incl = sum;
#pragma unroll
    for (int off = 1; off < 32; off <<= 1) {
        int u = __shfl_up_sync(0xffffffffu, incl, off);
        if (lane >= off) incl += u;
    }
    if (lane == 31) ssum[wid] = incl;
    __syncthreads();
    if (wid == 0) {
        int wv = (lane < 16) ? ssum[lane] : 0;
        int wi = wv;
#pragma unroll
        for (int off = 1; off < 16; off <<= 1) {
            int u = __shfl_up_sync(0xffffffffu, wi, off);
            if (lane >= off) wi += u;
        }
        if (lane < 16) ssum[lane] = wi - wv;   // exclusive warp offsets
    }
    __syncthreads();
    int excl = ssum[wid] + incl - sum;         // thread-exclusive prefix
#pragma unroll
    for (int i = 0; i < 4; i++) {
        int idx = base + t * 4 + i;
        if (idx < n) d_rowptr[idx] = excl;
        excl += v[i];
    }
    if (t == 511) d_blocksum[blockIdx.x] = ssum[15] + incl;
}

// finalize rowptr, compute dinv, zero pooled buffer
__global__ void k_scan_add(int n, int gsz, int nb) {
    __shared__ int s_pref;
    int base = blockIdx.x * 256;
    int t = threadIdx.x;
    if (t == 0) {
        int bucket = base >> 11;
        int p = 0;
        for (int j = 0; j < bucket; j++) p += d_blocksum[j];
        s_pref = p;
        if (blockIdx.x == 0) {
            int tot = 0;
            for (int j = 0; j < nb; j++) tot += d_blocksum[j];
            d_rowptr[n] = tot;
        }
    }
    __syncthreads();
    int i = base + t;
    if (i < n) {
        int r = d_rowptr[i] + s_pref;
        d_rowptr[i] = r;
        d_rowcur[i] = r;
        float deg = d_degw[i] + 1.0f;       // + self-loop weight
        d_dinv[i] = (deg > 0.f) ? rsqrtf(fmaxf(deg, 1e-12f)) : 0.f;
    }
    if (i < gsz) d_g[i] = 0.f;
}

// ---------------- GEMM0: m0 = dinv .* (x @ W0)  (fp16 out) -----------------
__global__ void __launch_bounds__(256) k_gemm0(const float* __restrict__ x,
                                               const float* __restrict__ W, int n) {
    __shared__ __align__(16) char sm[64 * 136 * 2 + 128 * 72 * 2];
    __shared__ float sdv[64];
    __half (*xs)[136] = reinterpret_cast<__half(*)[136]>(sm);
    __half (*ws)[72]  = reinterpret_cast<__half(*)[72]>(sm + 64 * 136 * 2);
    float  (*os)[68]  = reinterpret_cast<float(*)[68]>(sm);      // aliases xs

    int tid = threadIdx.x;
    int rowBase = blockIdx.x * 64;

    if (tid < 64) {
        int grow = rowBase + tid;
        sdv[tid] = (grow < n) ? d_dinv[grow] : 0.f;
    }
#pragma unroll
    for (int it = 0; it < 8; it++) {
        int idx = tid + it * 256;
        int r = idx >> 5, c = idx & 31;
        float4 v = make_float4(0.f, 0.f, 0.f, 0.f);
        int grow = rowBase + r;
        if (grow < n) v = *reinterpret_cast<const float4*>(x + (size_t)grow * 128 + c * 4);
        __half2 h0 = __floats2half2_rn(v.x, v.y);
        __half2 h1 = __floats2half2_rn(v.z, v.w);
        uint2 u; u.x = *reinterpret_cast<unsigned*>(&h0); u.y = *reinterpret_cast<unsigned*>(&h1);
        *reinterpret_cast<uint2*>(&xs[r][c * 4]) = u;
    }
#pragma unroll
    for (int it = 0; it < 8; it++) {
        int idx = tid + it * 256;
        int r = idx >> 4, c = idx & 15;
        float4 v = *reinterpret_cast<const float4*>(W + (size_t)r * 64 + c * 4);
        __half2 h0 = __floats2half2_rn(v.x, v.y);
        __half2 h1 = __floats2half2_rn(v.z, v.w);
        uint2 u; u.x = *reinterpret_cast<unsigned*>(&h0); u.y = *reinterpret_cast<unsigned*>(&h1);
        *reinterpret_cast<uint2*>(&ws[r][c * 4]) = u;
    }
    __syncthreads();

    int warp = tid >> 5;
    int rb = warp >> 1;          // 0..3 : row block (16 rows)
    int ch = warp & 1;           // 0..1 : column half (32 cols)

    wmma::fragment<wmma::accumulator, 16, 16, 16, float> c0, c1;
    wmma::fill_fragment(c0, 0.f);
    wmma::fill_fragment(c1, 0.f);
#pragma unroll
    for (int k = 0; k < 8; k++) {
        wmma::fragment<wmma::matrix_a, 16, 16, 16, __half, wmma::row_major> a;
        wmma::load_matrix_sync(a, &xs[rb * 16][k * 16], 136);
        wmma::fragment<wmma::matrix_b, 16, 16, 16, __half, wmma::row_major> b0, b1;
        wmma::load_matrix_sync(b0, &ws[k * 16][ch * 32], 72);
        wmma::load_matrix_sync(b1, &ws[k * 16][ch * 32 + 16], 72);
        wmma::mma_sync(c0, a, b0, c0);
        wmma::mma_sync(c1, a, b1, c1);
    }
    __syncthreads();             // xs no longer needed; reuse as float out
    wmma::store_matrix_sync(&os[rb * 16][ch * 32], c0, 68, wmma::mem_row_major);
    wmma::store_matrix_sync(&os[rb * 16][ch * 32 + 16], c1, 68, wmma::mem_row_major);
    __syncthreads();

#pragma unroll
    for (int it = 0; it < 8; it++) {
        int idx = tid + it * 256;
        int r = idx >> 5, c2 = idx & 31;
        int grow = rowBase + r;
        if (grow < n) {
            float dv = sdv[r];
            __half2 h = __floats2half2_rn(os[r][c2 * 2] * dv, os[r][c2 * 2 + 1] * dv);
            reinterpret_cast<__half2*>(d_m0 + (size_t)grow * 64)[c2] = h;
        }
    }
}

// ---------------- k_fill: packed CSR {src, raw weight} — no dinv needed ----
__global__ void k_fill(const int* __restrict__ src, const int* __restrict__ dst,
                       const float* __restrict__ w, int E) {
    int e = blockIdx.x * blockDim.x + threadIdx.x;
    if (e >= E) return;
    int d = dst[e];
    int2 pk; pk.x = src[e]; pk.y = __float_as_int(w[e]);
    int p = atomicAdd(&d_rowcur[d], 1);
    d_csr[p] = pk;
}

// ------- fused agg0 + GEMM1: m1 = dinv .* (relu(agg+b0) @ W1)  fp16 --------
// h[d] = relu(dinv[d]*(sum_e ew*m0[src] + m0[d]) + b0)   (m0 pre-scaled)
__global__ void __launch_bounds__(512) k_agg0_gemm1(const float* __restrict__ b0,
                                                    const float* __restrict__ W, int n) {
    __shared__ __align__(16) char sm[64 * 72 * 2 + 64 * 40 * 2];
    __shared__ float sdv[64];
    __half (*xs)[72] = reinterpret_cast<__half(*)[72]>(sm);
    __half (*ws)[40] = reinterpret_cast<__half(*)[40]>(sm + 64 * 72 * 2);
    float  (*os)[36] = reinterpret_cast<float(*)[36]>(sm);       // aliases xs

    int tid = threadIdx.x;
    int base = blockIdx.x * 64;
    int warp = tid >> 5;
    int lane = tid & 31;

    if (tid < 64) {
        int grow = base + tid;
        sdv[tid] = (grow < n) ? d_dinv[grow] : 0.f;
    }
    // load W1 [64,32] fp32 -> fp16 : 512 float4 jobs, one per thread
    {
        int r = tid >> 3, c = tid & 7;
        float4 v = *reinterpret_cast<const float4*>(W + (size_t)r * 32 + c * 4);
        __half2 h0 = __floats2half2_rn(v.x, v.y);
        __half2 h1 = __floats2half2_rn(v.z, v.w);
        uint2 u; u.x = *reinterpret_cast<unsigned*>(&h0); u.y = *reinterpret_cast<unsigned*>(&h1);
        *reinterpret_cast<uint2*>(&ws[r][c * 4]) = u;
    }
    __syncthreads();

    // aggregate 4 nodes per warp into xs rows
    const __half2* m = reinterpret_cast<const __half2*>(d_m0);
    float bx = b0[2 * lane], by = b0[2 * lane + 1];
#pragma unroll
    for (int i = 0; i < 4; i++) {
        int node = base + warp * 4 + i;
        int row = warp * 4 + i;
        if (node < n) {
            float2 mm = __half22float2(m[(size_t)node * 32 + lane]);
            float ax = mm.x, ay = mm.y;          // self term (pre-scaled m0)
            int e = d_rowptr[node], end = d_rowptr[node + 1];
            for (; e + 4 <= end; e += 4) {
                int2 p0 = d_csr[e], p1 = d_csr[e + 1], p2 = d_csr[e + 2], p3 = d_csr[e + 3];
                float2 v0 = __half22float2(m[(size_t)p0.x * 32 + lane]);
                float2 v1 = __half22float2(m[(size_t)p1.x * 32 + lane]);
                float2 v2 = __half22float2(m[(size_t)p2.x * 32 + lane]);
                float2 v3 = __half22float2(m[(size_t)p3.x * 32 + lane]);
                float w0 = __int_as_float(p0.y), w1 = __int_as_float(p1.y);
                float w2 = __int_as_float(p2.y), w3 = __int_as_float(p3.y);
                ax += w0 * v0.x; ay += w0 * v0.y;
                ax += w1 * v1.x; ay += w1 * v1.y;
                ax += w2 * v2.x; ay += w2 * v2.y;
                ax += w3 * v3.x; ay += w3 * v3.y;
            }
            for (; e < end; e++) {
                int2 p = d_csr[e];
                float2 v = __half22float2(m[(size_t)p.x * 32 + lane]);
                float w = __int_as_float(p.y);
                ax += w * v.x; ay += w * v.y;
            }
            float dv = sdv[row];
            ax = fmaxf(ax * dv + bx, 0.f); ay = fmaxf(ay * dv + by, 0.f);
            *reinterpret_cast<__half2*>(&xs[row][lane * 2]) = __floats2half2_rn(ax, ay);
        } else {
            *reinterpret_cast<__half2*>(&xs[row][lane * 2]) = __half2half2(__float2half(0.f));
        }
    }
    __syncthreads();

    // wmma: warps 0..7, each computes one 16x16 block of the 64x32 output
    if (warp < 8) {
        int rb = warp >> 1;      // 0..3
        int cb = warp & 1;       // 0..1
        wmma::fragment<wmma::accumulator, 16, 16, 16, float> c0;
        wmma::fill_fragment(c0, 0.f);
#pragma unroll
        for (int k = 0; k < 4; k++) {
            wmma::fragment<wmma::matrix_a, 16, 16, 16, __half, wmma::row_major> a;
            wmma::load_matrix_sync(a, &xs[rb * 16][k * 16], 72);
            wmma::fragment<wmma::matrix_b, 16, 16, 16, __half, wmma::row_major> b;
            wmma::load_matrix_sync(b, &ws[k * 16][cb * 16], 40);
            wmma::mma_sync(c0, a, b, c0);
        }
        __syncthreads();         // all mma reads of xs done
        wmma::store_matrix_sync(&os[rb * 16][cb * 16], c0, 36, wmma::mem_row_major);
    } else {
        __syncthreads();
    }
    __syncthreads();

    // write out m1 = dinv .* os, fp16 : 64 rows x 16 half2 = 1024 jobs
#pragma unroll
    for (int it = 0; it < 2; it++) {
        int idx = tid + it * 512;
        int r = idx >> 4, c2 = idx & 15;
        int grow = base + r;
        if (grow < n) {
            float dv = sdv[r];
            __half2 h = __floats2half2_rn(os[r][c2 * 2] * dv, os[r][c2 * 2 + 1] * dv);
            reinterpret_cast<__half2*>(d_m1 + (size_t)grow * 32)[c2] = h;
        }
    }
}

// ---------------- agg1 + pooling: g[graph] += relu(agg + b1) ---------------
__global__ void __launch_bounds__(256) k_agg1(const float* __restrict__ b1,
                                              const int* __restrict__ ngi, int n) {
    int warp = (blockIdx.x * blockDim.x + threadIdx.x) >> 5;
    int lane = threadIdx.x & 31;
    if (warp >= n) return;
    float acc = __half2float(d_m1[(size_t)warp * 32 + lane]);   // self (pre-scaled)
    int e = d_rowptr[warp], end = d_rowptr[warp + 1];
    for (; e + 4 <= end; e += 4) {
        int2 p0 = d_csr[e], p1 = d_csr[e + 1], p2 = d_csr[e + 2], p3 = d_csr[e + 3];
        acc += __int_as_float(p0.y) * __half2float(d_m1[(size_t)p0.x * 32 + lane]);
        acc += __int_as_float(p1.y) * __half2float(d_m1[(size_t)p1.x * 32 + lane]);
        acc += __int_as_float(p2.y) * __half2float(d_m1[(size_t)p2.x * 32 + lane]);
        acc += __int_as_float(p3.y) * __half2float(d_m1[(size_t)p3.x * 32 + lane]);
    }
    for (; e < end; e++) {
        int2 p = d_csr[e];
        acc += __int_as_float(p.y) * __half2float(d_m1[(size_t)p.x * 32 + lane]);
    }
    float h = fmaxf(acc * d_dinv[warp] + b1[lane], 0.f);
    int g = ngi[warp];
    atomicAdd(&d_g[(size_t)g * 32 + lane], h);
}

// ---------------- MLP head: logits = relu(g@Wm1+bm1)@Wm2+bm2 ---------------
__global__ void __launch_bounds__(128) k_mlp(const float* __restrict__ Wm1,
                                             const float* __restrict__ bm1,
                                             const float* __restrict__ Wm2,
                                             const float* __restrict__ bm2,
                                             float* __restrict__ out, int G) {
    int gi = blockIdx.x;
    if (gi >= G) return;
    __shared__ float gs[32];
    __shared__ float red0[4], red1[4];
    int t = threadIdx.x;
    if (t < 32) gs[t] = d_g[(size_t)gi * 32 + t];
    __syncthreads();
    float acc = bm1[t];
#pragma unroll
    for (int k = 0; k < 32; k++) acc += gs[k] * Wm1[k * 128 + t];
    float h = fmaxf(acc, 0.f);
    float p0 = h * Wm2[t * 2 + 0];
    float p1 = h * Wm2[t * 2 + 1];
#pragma unroll
    for (int off = 16; off > 0; off >>= 1) {
        p0 += __shfl_down_sync(0xffffffffu, p0, off);
        p1 += __shfl_down_sync(0xffffffffu, p1, off);
    }
    if ((t & 31) == 0) { red0[t >> 5] = p0; red1[t >> 5] = p1; }
    __syncthreads();
    if (t == 0) {
        out[gi * 2 + 0] = red0[0] + red0[1] + red0[2] + red0[3] + bm2[0];
        out[gi * 2 + 1] = red1[0] + red1[1] + red1[2] + red1[3] + bm2[1];
    }
}

// ---------------------------------------------------------------------------
extern "C" void kernel_launch(void* const* d_in, const int* in_sizes, int n_in,
                              void* d_out, int out_size) {
    const float* x   = (const float*)d_in[0];
    const int*   ei  = (const int*)d_in[1];
    const float* ew  = (const float*)d_in[2];
    const int*   ngi = (const int*)d_in[3];
    const float* W0  = (const float*)d_in[4];
    const float* b0  = (const float*)d_in[5];
    const float* W1  = (const float*)d_in[6];
    const float* b1  = (const float*)d_in[7];
    const float* Wm1 = (const float*)d_in[8];
    const float* bm1 = (const float*)d_in[9];
    const float* Wm2 = (const float*)d_in[10];
    const float* bm2 = (const float*)d_in[11];
    float* out = (float*)d_out;

    int N = in_sizes[3];            // node_graph_index count
    int E = in_sizes[1] / 2;        // edge_index is [2, E]
    int G = out_size / 2;
    if (N > MAXN) N = MAXN;
    if (E > MAXE) E = MAXE;
    if (G > MAXG) G = MAXG;

    const int* e_src = ei;
    const int* e_dst = ei + E;

    int nb = (N + 2047) / 2048;     // scan blocks (<=64)

    // one-time side-stream + events (created outside any capture; reused in it)
    static cudaStream_t s_aux = nullptr;
    static cudaEvent_t  s_fork = nullptr, s_join = nullptr;
    if (s_aux == nullptr) {
        cudaStreamCreateWithFlags(&s_aux, cudaStreamNonBlocking);
        cudaEventCreateWithFlags(&s_fork, cudaEventDisableTiming);
        cudaEventCreateWithFlags(&s_join, cudaEventDisableTiming);
    }

    // CSR count + scan (produces rowptr, rowcur, dinv)
    k_zero<<<(N + 255) / 256, 256>>>(N);
    k_deg<<<(E + 255) / 256, 256>>>(e_dst, ew, E);
    k_scan_partial<<<nb, 512>>>(N);
    k_scan_add<<<(N + 255) / 256, 256>>>(N, G * 32, nb);

    // fork: gemm0 (needs dinv) overlaps with CSR fill
    cudaEventRecord(s_fork, 0);
    cudaStreamWaitEvent(s_aux, s_fork, 0);
    k_gemm0<<<(N + 63) / 64, 256, 0, s_aux>>>(x, W0, N);
    cudaEventRecord(s_join, s_aux);

    k_fill<<<(E + 255) / 256, 256>>>(e_src, e_dst, ew, E);

    // join, then fused layer-1-agg + layer-2-GEMM, agg1+pool, MLP head
    cudaStreamWaitEvent(0, s_join, 0);
    k_agg0_gemm1<<<(N + 63) / 64, 512>>>(b0, W1, N);
    k_agg1<<<(N + 7) / 8, 256>>>(b1, ngi, N);
    k_mlp<<<G, 128>>>(Wm1, bm1, Wm2, bm2, out, G);
}